// round 9
// baseline (speedup 1.0000x reference)
#include <cuda_runtime.h>
#include <math.h>

#define N_NODES 100000
#define E_MAX   1600000
#define C 128
#define OUTC 64
#define AST 132          // padded stride, A tile (row-major, k contiguous)
#define BT_ST 132        // padded stride, transposed B tile (k contiguous)
#define SCAN_BS 1024
#define SCAN_NB ((N_NODES + SCAN_BS - 1) / SCAN_BS)   // 98

// ---------------- scratch (static device globals: allocation-free) ----------
// Referenced ONLY from device code (host-side use of __device__ symbols gives
// the host shadow address — round-3 lesson).
__device__ int   g_cnt[N_NODES];        // in-degree (edges only, no self-loop)
__device__ int   g_rowstart[N_NODES];   // CSR row offsets (exclusive scan)
__device__ int   g_cursor[N_NODES];     // fill cursors
__device__ int   g_bsum[SCAN_NB];       // scan block sums
__device__ int   g_csrc[E_MAX];         // CSR: src node per incoming edge slot
__device__ float g_dinv[N_NODES];
__device__ float g_aggX[(size_t)N_NODES * C];
__device__ float g_h[(size_t)N_NODES * C];
__device__ float g_aggH[(size_t)N_NODES * C];

// ---------------- CSR build --------------------------------------------------
__global__ void k_cnt_init() {
    int i = blockIdx.x * blockDim.x + threadIdx.x;
    if (i < N_NODES) g_cnt[i] = 0;
}

__global__ void k_count(const int* __restrict__ dst, int n_edges) {
    int e = blockIdx.x * blockDim.x + threadIdx.x;
    if (e < n_edges) atomicAdd(&g_cnt[dst[e]], 1);
}

// pass 1: per-block inclusive scan -> exclusive per element + block sums
__global__ void k_scan_block() {
    __shared__ int sh[SCAN_BS];
    int tid = threadIdx.x;
    int i = blockIdx.x * SCAN_BS + tid;
    int v = (i < N_NODES) ? g_cnt[i] : 0;
    sh[tid] = v;
    __syncthreads();
#pragma unroll
    for (int off = 1; off < SCAN_BS; off <<= 1) {
        int t = (tid >= off) ? sh[tid - off] : 0;
        __syncthreads();
        sh[tid] += t;
        __syncthreads();
    }
    if (i < N_NODES) g_rowstart[i] = sh[tid] - v;   // exclusive
    if (tid == SCAN_BS - 1) g_bsum[blockIdx.x] = sh[tid];
}

// pass 2 (merged): each 256-thread block lies in scan-block sb = b>>2;
// reduce g_bsum[0..sb-1] locally, add offset, init cursors, compute dinv.
__global__ void k_scan_add() {
    __shared__ int ssum[128];
    int tid = threadIdx.x;
    int sb = blockIdx.x >> 2;   // 1024/256 = 4 blocks per scan-block, aligned
    if (tid < 128) ssum[tid] = (tid < sb) ? g_bsum[tid] : 0;
    __syncthreads();
#pragma unroll
    for (int s = 64; s > 0; s >>= 1) {
        if (tid < s) ssum[tid] += ssum[tid + s];
        __syncthreads();
    }
    int off = ssum[0];
    int i = blockIdx.x * 256 + tid;
    if (i < N_NODES) {
        g_rowstart[i] += off;
        g_cursor[i] = 0;
        g_dinv[i] = rsqrtf((float)g_cnt[i] + 1.0f);
    }
}

__global__ void k_fill(const int* __restrict__ src, const int* __restrict__ dst,
                       int n_edges) {
    int e = blockIdx.x * blockDim.x + threadIdx.x;
    if (e >= n_edges) return;
    int d = dst[e];
    int p = atomicAdd(&g_cursor[d], 1);
    g_csrc[g_rowstart[d] + p] = src[e];
}

// ---------------- gather-aggregate: one warp per destination node ------------
// agg[n] = dinv[n]^2 * srcmat[n] + sum_{s in in(n)} dinv[n]*dinv[s]*srcmat[s]
// PHASE 0: x -> g_aggX     PHASE 1: g_h -> g_aggH
template<int PHASE>
__global__ void k_agg(const float* __restrict__ x) {
    const float* srcmat = (PHASE == 0) ? x : g_h;
    float* agg = (PHASE == 0) ? g_aggX : g_aggH;

    unsigned node = (blockIdx.x * blockDim.x + threadIdx.x) >> 5;
    unsigned lane = threadIdx.x & 31;
    if (node >= N_NODES) return;

    float din = g_dinv[node];
    // self-loop init
    float4 acc = reinterpret_cast<const float4*>(srcmat + (size_t)node * C)[lane];
    float cself = din * din;
    acc.x *= cself; acc.y *= cself; acc.z *= cself; acc.w *= cself;

    int beg = g_rowstart[node];
    int cnt = g_cnt[node];
    int j = 0;
    // 4-way unrolled edge loop: 4 rows in flight per warp (MLP)
    for (; j + 3 < cnt; j += 4) {
        int s0 = g_csrc[beg + j];
        int s1 = g_csrc[beg + j + 1];
        int s2 = g_csrc[beg + j + 2];
        int s3 = g_csrc[beg + j + 3];
        float c0 = din * g_dinv[s0];
        float c1 = din * g_dinv[s1];
        float c2 = din * g_dinv[s2];
        float c3 = din * g_dinv[s3];
        float4 v0 = reinterpret_cast<const float4*>(srcmat + (size_t)s0 * C)[lane];
        float4 v1 = reinterpret_cast<const float4*>(srcmat + (size_t)s1 * C)[lane];
        float4 v2 = reinterpret_cast<const float4*>(srcmat + (size_t)s2 * C)[lane];
        float4 v3 = reinterpret_cast<const float4*>(srcmat + (size_t)s3 * C)[lane];
        acc.x += c0 * v0.x + c1 * v1.x + c2 * v2.x + c3 * v3.x;
        acc.y += c0 * v0.y + c1 * v1.y + c2 * v2.y + c3 * v3.y;
        acc.z += c0 * v0.z + c1 * v1.z + c2 * v2.z + c3 * v3.z;
        acc.w += c0 * v0.w + c1 * v1.w + c2 * v2.w + c3 * v3.w;
    }
    for (; j < cnt; j++) {
        int s = g_csrc[beg + j];
        float c = din * g_dinv[s];
        float4 v = reinterpret_cast<const float4*>(srcmat + (size_t)s * C)[lane];
        acc.x += c * v.x; acc.y += c * v.y; acc.z += c * v.z; acc.w += c * v.w;
    }
    reinterpret_cast<float4*>(agg + (size_t)node * C)[lane] = acc;
}

// ---------------- fused GEMM: out[m,128] = A[m,128] @ B[128,128] + bias ------
// 128x128 block tile, 256 threads (16 tx x 16 ty), 8x8 microtile:
// rows r = ty+16i, cols c = tx+16j. Fragments are vectorized over k:
//   a_frag: float4 from As[r][k..k+3]   (A row-major, k contiguous)
//   b_frag: float4 from Bt[c][k..k+3]   (B transposed once at tile load)
// Per 4-k step: 16 LDS.128 per thread for 256 FMA -> crossbar ~30% of cap
// (was 100% with scalar LDS); 1-chunk prefetch pipeline hides LDS latency.
// MODE 0: A=g_aggX, B=W1, bias=b1, out=g_h; epilogue ReLU + row L2-normalize.
// MODE 1: A=g_aggH, B=[Wmu|Wls] (inline concat), bias=[bmu|bls],
//         out=d_out split into mu / logstd regions.
template<int MODE>
__global__ void __launch_bounds__(256)
k_gemm(const float* __restrict__ Bp, const float* __restrict__ Bp2,
       const float* __restrict__ biasp, const float* __restrict__ biasp2,
       float* __restrict__ outp) {
    const float* A = (MODE == 0) ? g_aggX : g_aggH;
    float* out     = (MODE == 0) ? g_h : outp;
    const int M = N_NODES;

    extern __shared__ float sm[];
    float* As = sm;              // 128 x AST   (row-major)
    float* Bt = sm + 128 * AST;  // 128 x BT_ST (transposed: Bt[c][k])

    int tid = threadIdx.x;
    int m0  = blockIdx.x * 128;

    // load B transposed: scalar gmem reads (coalesced), STS deg-4 (one-time).
    for (int i = tid; i < C * C; i += 256) {
        int k = i >> 7, c = i & 127;
        float v;
        if (MODE == 0) {
            v = Bp[k * C + c];
        } else {
            v = (c < OUTC) ? Bp[k * OUTC + c] : Bp2[k * OUTC + (c - OUTC)];
        }
        Bt[c * BT_ST + k] = v;
    }
    // load A tile (128 rows, guarded), row-major padded stride
    for (int i = tid; i < 128 * (C / 4); i += 256) {
        int r  = i >> 5;
        int c4 = i & 31;
        float4 v = make_float4(0.f, 0.f, 0.f, 0.f);
        if (m0 + r < M)
            v = reinterpret_cast<const float4*>(A + (size_t)(m0 + r) * C)[c4];
        reinterpret_cast<float4*>(As + r * AST)[c4] = v;
    }
    __syncthreads();

    int tx = tid & 15, ty = tid >> 4;

    float acc[8][8];
#pragma unroll
    for (int i = 0; i < 8; i++)
#pragma unroll
        for (int j = 0; j < 8; j++) acc[i][j] = 0.f;

    float4 a_cur[8], b_cur[8];
#pragma unroll
    for (int i = 0; i < 8; i++)
        a_cur[i] = *reinterpret_cast<const float4*>(&As[(ty + 16 * i) * AST]);
#pragma unroll
    for (int j = 0; j < 8; j++)
        b_cur[j] = *reinterpret_cast<const float4*>(&Bt[(tx + 16 * j) * BT_ST]);

#pragma unroll 1
    for (int kk = 0; kk < C - 4; kk += 4) {
        float4 a_nxt[8], b_nxt[8];
#pragma unroll
        for (int i = 0; i < 8; i++)
            a_nxt[i] = *reinterpret_cast<const float4*>(&As[(ty + 16 * i) * AST + kk + 4]);
#pragma unroll
        for (int j = 0; j < 8; j++)
            b_nxt[j] = *reinterpret_cast<const float4*>(&Bt[(tx + 16 * j) * BT_ST + kk + 4]);
#pragma unroll
        for (int i = 0; i < 8; i++)
#pragma unroll
            for (int j = 0; j < 8; j++) {
                acc[i][j] = fmaf(a_cur[i].x, b_cur[j].x, acc[i][j]);
                acc[i][j] = fmaf(a_cur[i].y, b_cur[j].y, acc[i][j]);
                acc[i][j] = fmaf(a_cur[i].z, b_cur[j].z, acc[i][j]);
                acc[i][j] = fmaf(a_cur[i].w, b_cur[j].w, acc[i][j]);
            }
#pragma unroll
        for (int i = 0; i < 8; i++) a_cur[i] = a_nxt[i];
#pragma unroll
        for (int j = 0; j < 8; j++) b_cur[j] = b_nxt[j];
    }
#pragma unroll
    for (int i = 0; i < 8; i++)
#pragma unroll
        for (int j = 0; j < 8; j++) {
            acc[i][j] = fmaf(a_cur[i].x, b_cur[j].x, acc[i][j]);
            acc[i][j] = fmaf(a_cur[i].y, b_cur[j].y, acc[i][j]);
            acc[i][j] = fmaf(a_cur[i].z, b_cur[j].z, acc[i][j]);
            acc[i][j] = fmaf(a_cur[i].w, b_cur[j].w, acc[i][j]);
        }

    if (MODE == 0) {
        // bias + ReLU + row L2 normalize (second ReLU in ref is a no-op: h>=0)
#pragma unroll
        for (int i = 0; i < 8; i++) {
            float ss = 0.f;
#pragma unroll
            for (int j = 0; j < 8; j++) {
                float v = fmaxf(acc[i][j] + biasp[tx + 16 * j], 0.f);
                acc[i][j] = v;
                ss += v * v;
            }
            // reduce across the 16 tx lanes (bits 0..3 of lane id)
#pragma unroll
            for (int msk = 1; msk < 16; msk <<= 1)
                ss += __shfl_xor_sync(0xffffffffu, ss, msk);
            float scale = 1.f / fmaxf(sqrtf(ss), 1e-12f);
            int r = m0 + ty + 16 * i;
            if (r < M) {
#pragma unroll
                for (int j = 0; j < 8; j++)
                    out[(size_t)r * C + tx + 16 * j] = acc[i][j] * scale;
            }
        }
    } else {
        // split epilogue: cols [0,64) -> mu, [64,128) -> logstd
#pragma unroll
        for (int i = 0; i < 8; i++) {
            int r = m0 + ty + 16 * i;
            if (r < M) {
#pragma unroll
                for (int j = 0; j < 8; j++) {
                    int c = tx + 16 * j;
                    float bias = (c < OUTC) ? biasp[c] : biasp2[c - OUTC];
                    float v = acc[i][j] + bias;
                    size_t off = (c < OUTC)
                        ? (size_t)r * OUTC + c
                        : (size_t)N_NODES * OUTC + (size_t)r * OUTC + (c - OUTC);
                    out[off] = v;
                }
            }
        }
    }
}

// ---------------- launch -----------------------------------------------------
extern "C" void kernel_launch(void* const* d_in, const int* in_sizes, int n_in,
                              void* d_out, int out_size) {
    const float* x   = (const float*)d_in[0];
    const int*   ei  = (const int*)  d_in[1];
    const float* W1  = (const float*)d_in[2];
    const float* b1  = (const float*)d_in[3];
    const float* Wmu = (const float*)d_in[4];
    const float* bmu = (const float*)d_in[5];
    const float* Wls = (const float*)d_in[6];
    const float* bls = (const float*)d_in[7];
    float* out = (float*)d_out;

    const int n_edges = in_sizes[1] / 2;     // edge_index is [2, E]
    const int* src = ei;                     // edge_index[0]
    const int* dst = ei + n_edges;           // edge_index[1]

    const int smem = (128 * AST + 128 * BT_ST) * (int)sizeof(float);  // ~132 KB

    static bool configured = false;
    if (!configured) {
        cudaFuncSetAttribute(k_gemm<0>, cudaFuncAttributeMaxDynamicSharedMemorySize, smem);
        cudaFuncSetAttribute(k_gemm<1>, cudaFuncAttributeMaxDynamicSharedMemorySize, smem);
        configured = true;
    }

    // ---- CSR build (once, reused by both aggregations) ----
    k_cnt_init<<<(N_NODES + 255) / 256, 256>>>();
    k_count<<<(n_edges + 255) / 256, 256>>>(dst, n_edges);
    k_scan_block<<<SCAN_NB, SCAN_BS>>>();
    k_scan_add<<<(N_NODES + 255) / 256, 256>>>();
    k_fill<<<(n_edges + 255) / 256, 256>>>(src, dst, n_edges);

    // ---- layer 1: aggX = A_norm @ x ; h = rownorm(relu(aggX @ W1 + b1)) ----
    {
        unsigned t = (unsigned)N_NODES * 32u;
        k_agg<0><<<(t + 255) / 256, 256>>>(x);
    }
    k_gemm<0><<<(N_NODES + 127) / 128, 256, smem>>>(W1, nullptr, b1, nullptr, nullptr);

    // ---- layer 2: aggH = A_norm @ h ; [mu|logstd] = aggH @ [Wmu|Wls] + b ----
    {
        unsigned t = (unsigned)N_NODES * 32u;
        k_agg<1><<<(t + 255) / 256, 256>>>(nullptr);
    }
    k_gemm<1><<<(N_NODES + 127) / 128, 256, smem>>>(Wmu, Wls, bmu, bls, out);
}

// round 10
// speedup vs baseline: 1.0595x; 1.0595x over previous
#include <cuda_runtime.h>
#include <math.h>

#define N_NODES 100000
#define E_MAX   1600000
#define C 128
#define OUTC 64
#define AST 132          // padded stride, A tile (row-major, k contiguous)
#define SCAN_BS 1024
#define SCAN_NB ((N_NODES + SCAN_BS - 1) / SCAN_BS)   // 98

// packed fp32 FMA (sm_103a FFMA2) — only reachable via PTX fma.rn.f32x2
#define FMA_F32X2(d, a, b, c) \
    asm("fma.rn.f32x2 %0, %1, %2, %3;" : "=l"(d) : "l"(a), "l"(b), "l"(c))
#define PACK_DUP_F32X2(d, v) \
    asm("mov.b64 %0, {%1, %1};" : "=l"(d) : "r"(__float_as_uint(v)))
#define UNPACK_F32X2(lo, hi, p) do {                                        \
    unsigned _ulo, _uhi;                                                    \
    asm("mov.b64 {%0, %1}, %2;" : "=r"(_ulo), "=r"(_uhi) : "l"(p));         \
    lo = __uint_as_float(_ulo); hi = __uint_as_float(_uhi); } while (0)

// ---------------- scratch (static device globals: allocation-free) ----------
// Referenced ONLY from device code (host-side use of __device__ symbols gives
// the host shadow address — round-3 lesson).
__device__ int   g_cnt[N_NODES];        // in-degree (edges only, no self-loop)
__device__ int   g_rowstart[N_NODES];   // CSR row offsets (exclusive scan)
__device__ int   g_cursor[N_NODES];     // fill cursors
__device__ int   g_bsum[SCAN_NB];       // scan block sums
__device__ int   g_csrc[E_MAX];         // CSR: src node per incoming edge slot
__device__ float g_dinv[N_NODES];
__device__ float g_aggX[(size_t)N_NODES * C];
__device__ float g_h[(size_t)N_NODES * C];
__device__ float g_aggH[(size_t)N_NODES * C];

// ---------------- CSR build --------------------------------------------------
__global__ void k_cnt_init() {
    int i = blockIdx.x * blockDim.x + threadIdx.x;
    if (i < N_NODES) g_cnt[i] = 0;
}

__global__ void k_count(const int* __restrict__ dst, int n_edges) {
    int e = blockIdx.x * blockDim.x + threadIdx.x;
    if (e < n_edges) atomicAdd(&g_cnt[dst[e]], 1);
}

// pass 1: per-block inclusive scan -> exclusive per element + block sums
__global__ void k_scan_block() {
    __shared__ int sh[SCAN_BS];
    int tid = threadIdx.x;
    int i = blockIdx.x * SCAN_BS + tid;
    int v = (i < N_NODES) ? g_cnt[i] : 0;
    sh[tid] = v;
    __syncthreads();
#pragma unroll
    for (int off = 1; off < SCAN_BS; off <<= 1) {
        int t = (tid >= off) ? sh[tid - off] : 0;
        __syncthreads();
        sh[tid] += t;
        __syncthreads();
    }
    if (i < N_NODES) g_rowstart[i] = sh[tid] - v;   // exclusive
    if (tid == SCAN_BS - 1) g_bsum[blockIdx.x] = sh[tid];
}

// pass 2 (merged): each 256-thread block lies in scan-block sb = b>>2;
// reduce g_bsum[0..sb-1] locally, add offset, init cursors, compute dinv.
__global__ void k_scan_add() {
    __shared__ int ssum[128];
    int tid = threadIdx.x;
    int sb = blockIdx.x >> 2;   // 1024/256 = 4 blocks per scan-block, aligned
    if (tid < 128) ssum[tid] = (tid < sb) ? g_bsum[tid] : 0;
    __syncthreads();
#pragma unroll
    for (int s = 64; s > 0; s >>= 1) {
        if (tid < s) ssum[tid] += ssum[tid + s];
        __syncthreads();
    }
    int off = ssum[0];
    int i = blockIdx.x * 256 + tid;
    if (i < N_NODES) {
        g_rowstart[i] += off;
        g_cursor[i] = 0;
        g_dinv[i] = rsqrtf((float)g_cnt[i] + 1.0f);
    }
}

__global__ void k_fill(const int* __restrict__ src, const int* __restrict__ dst,
                       int n_edges) {
    int e = blockIdx.x * blockDim.x + threadIdx.x;
    if (e >= n_edges) return;
    int d = dst[e];
    int p = atomicAdd(&g_cursor[d], 1);
    g_csrc[g_rowstart[d] + p] = src[e];
}

// ---------------- gather-aggregate: one warp per destination node ------------
// agg[n] = dinv[n]^2 * srcmat[n] + sum_{s in in(n)} dinv[n]*dinv[s]*srcmat[s]
// PHASE 0: x -> g_aggX     PHASE 1: g_h -> g_aggH
template<int PHASE>
__global__ void k_agg(const float* __restrict__ x) {
    const float* srcmat = (PHASE == 0) ? x : g_h;
    float* agg = (PHASE == 0) ? g_aggX : g_aggH;

    unsigned node = (blockIdx.x * blockDim.x + threadIdx.x) >> 5;
    unsigned lane = threadIdx.x & 31;
    if (node >= N_NODES) return;

    float din = g_dinv[node];
    // self-loop init
    float4 acc = reinterpret_cast<const float4*>(srcmat + (size_t)node * C)[lane];
    float cself = din * din;
    acc.x *= cself; acc.y *= cself; acc.z *= cself; acc.w *= cself;

    int beg = g_rowstart[node];
    int cnt = g_cnt[node];
    int j = 0;
    // 4-way unrolled edge loop: 4 rows in flight per warp (MLP)
    for (; j + 3 < cnt; j += 4) {
        int s0 = g_csrc[beg + j];
        int s1 = g_csrc[beg + j + 1];
        int s2 = g_csrc[beg + j + 2];
        int s3 = g_csrc[beg + j + 3];
        float c0 = din * g_dinv[s0];
        float c1 = din * g_dinv[s1];
        float c2 = din * g_dinv[s2];
        float c3 = din * g_dinv[s3];
        float4 v0 = reinterpret_cast<const float4*>(srcmat + (size_t)s0 * C)[lane];
        float4 v1 = reinterpret_cast<const float4*>(srcmat + (size_t)s1 * C)[lane];
        float4 v2 = reinterpret_cast<const float4*>(srcmat + (size_t)s2 * C)[lane];
        float4 v3 = reinterpret_cast<const float4*>(srcmat + (size_t)s3 * C)[lane];
        acc.x += c0 * v0.x + c1 * v1.x + c2 * v2.x + c3 * v3.x;
        acc.y += c0 * v0.y + c1 * v1.y + c2 * v2.y + c3 * v3.y;
        acc.z += c0 * v0.z + c1 * v1.z + c2 * v2.z + c3 * v3.z;
        acc.w += c0 * v0.w + c1 * v1.w + c2 * v2.w + c3 * v3.w;
    }
    for (; j < cnt; j++) {
        int s = g_csrc[beg + j];
        float c = din * g_dinv[s];
        float4 v = reinterpret_cast<const float4*>(srcmat + (size_t)s * C)[lane];
        acc.x += c * v.x; acc.y += c * v.y; acc.z += c * v.z; acc.w += c * v.w;
    }
    reinterpret_cast<float4*>(agg + (size_t)node * C)[lane] = acc;
}

__device__ __forceinline__ float f4get(const float4& v, int dk) {
    return dk == 0 ? v.x : dk == 1 ? v.y : dk == 2 ? v.z : v.w;
}

// ---------------- fused GEMM (packed f32x2): out = A @ B + bias --------------
// 128x128 block tile, 256 threads (16 tx x 16 ty).
// Thread owns rows r = ty + 16*i (i<8) and ADJACENT column pairs
// c = 2*tx + 32*j' (j'<4): the b operand (B[k][c], B[k][c+1]) is one aligned
// LDS.64 that is already an f32x2 pair; accumulators are f32x2; the a operand
// is broadcast-packed via mov.b64 {a,a}. Per k per thread: 8 packs + 32 FFMA2
// (vs 64 FFMA before) -> ~2x the scalar-FFMA rate ceiling.
// MODE 0: A=g_aggX, B=W1, bias=b1, out=g_h; epilogue ReLU + row L2-normalize.
// MODE 1: A=g_aggH, B=[Wmu|Wls] (inline concat), bias=[bmu|bls],
//         out=d_out split into mu / logstd regions.
template<int MODE>
__global__ void __launch_bounds__(256)
k_gemm(const float* __restrict__ Bp, const float* __restrict__ Bp2,
       const float* __restrict__ biasp, const float* __restrict__ biasp2,
       float* __restrict__ outp) {
    const float* A = (MODE == 0) ? g_aggX : g_aggH;
    float* out     = (MODE == 0) ? g_h : outp;
    const int M = N_NODES;

    extern __shared__ float sm[];
    float* As = sm;              // 128 x AST (row-major, k contiguous)
    float* Bs = sm + 128 * AST;  // 128 x 128 (row-major: Bs[k][c])

    int tid = threadIdx.x;
    int m0  = blockIdx.x * 128;

    // load B row-major. MODE 1 concatenates Wmu|Wls on the fly
    // (each float4 lies wholly in one 64-col half).
    for (int i = tid; i < C * C / 4; i += 256) {
        float4 v;
        if (MODE == 0) {
            v = reinterpret_cast<const float4*>(Bp)[i];
        } else {
            int k = i >> 5;          // row
            int c4 = (i & 31) * 4;   // col
            v = (c4 < OUTC)
                ? *reinterpret_cast<const float4*>(Bp  + k * OUTC + c4)
                : *reinterpret_cast<const float4*>(Bp2 + k * OUTC + (c4 - OUTC));
        }
        reinterpret_cast<float4*>(Bs)[i] = v;
    }
    // load A tile (128 rows, guarded), row-major padded stride
    for (int i = tid; i < 128 * (C / 4); i += 256) {
        int r  = i >> 5;
        int c4 = i & 31;
        float4 v = make_float4(0.f, 0.f, 0.f, 0.f);
        if (m0 + r < M)
            v = reinterpret_cast<const float4*>(A + (size_t)(m0 + r) * C)[c4];
        reinterpret_cast<float4*>(As + r * AST)[c4] = v;
    }
    __syncthreads();

    int tx = tid & 15, ty = tid >> 4;
    int cbase = 2 * tx;              // column pair base; pairs at cbase + 32*j'

    unsigned long long acc2[8][4];
#pragma unroll
    for (int i = 0; i < 8; i++)
#pragma unroll
        for (int j = 0; j < 4; j++) acc2[i][j] = 0ULL;

    float4 a_cur[8];
#pragma unroll
    for (int i = 0; i < 8; i++)
        a_cur[i] = *reinterpret_cast<const float4*>(&As[(ty + 16 * i) * AST]);

#pragma unroll 1
    for (int kk = 0; kk < C - 4; kk += 4) {
        float4 a_nxt[8];
#pragma unroll
        for (int i = 0; i < 8; i++)
            a_nxt[i] = *reinterpret_cast<const float4*>(&As[(ty + 16 * i) * AST + kk + 4]);
#pragma unroll
        for (int dk = 0; dk < 4; dk++) {
            int k = kk + dk;
            unsigned long long b2[4];
#pragma unroll
            for (int j = 0; j < 4; j++)
                b2[j] = *reinterpret_cast<const unsigned long long*>(
                            &Bs[k * C + cbase + 32 * j]);
#pragma unroll
            for (int i = 0; i < 8; i++) {
                unsigned long long a2;
                PACK_DUP_F32X2(a2, f4get(a_cur[i], dk));
#pragma unroll
                for (int j = 0; j < 4; j++)
                    FMA_F32X2(acc2[i][j], a2, b2[j], acc2[i][j]);
            }
        }
#pragma unroll
        for (int i = 0; i < 8; i++) a_cur[i] = a_nxt[i];
    }
    // tail chunk (kk = C-4)
#pragma unroll
    for (int dk = 0; dk < 4; dk++) {
        int k = C - 4 + dk;
        unsigned long long b2[4];
#pragma unroll
        for (int j = 0; j < 4; j++)
            b2[j] = *reinterpret_cast<const unsigned long long*>(
                        &Bs[k * C + cbase + 32 * j]);
#pragma unroll
        for (int i = 0; i < 8; i++) {
            unsigned long long a2;
            PACK_DUP_F32X2(a2, f4get(a_cur[i], dk));
#pragma unroll
            for (int j = 0; j < 4; j++)
                FMA_F32X2(acc2[i][j], a2, b2[j], acc2[i][j]);
        }
    }

    if (MODE == 0) {
        // bias + ReLU + row L2 normalize (second ReLU in ref is a no-op: h>=0)
#pragma unroll
        for (int i = 0; i < 8; i++) {
            float lo[4], hi[4];
            float ss = 0.f;
#pragma unroll
            for (int j = 0; j < 4; j++) {
                int c = cbase + 32 * j;
                float l, h;
                UNPACK_F32X2(l, h, acc2[i][j]);
                l = fmaxf(l + biasp[c], 0.f);
                h = fmaxf(h + biasp[c + 1], 0.f);
                lo[j] = l; hi[j] = h;
                ss += l * l + h * h;
            }
            // reduce across the 16 tx lanes (bits 0..3 of lane id)
#pragma unroll
            for (int msk = 1; msk < 16; msk <<= 1)
                ss += __shfl_xor_sync(0xffffffffu, ss, msk);
            float scale = 1.f / fmaxf(sqrtf(ss), 1e-12f);
            int r = m0 + ty + 16 * i;
            if (r < M) {
#pragma unroll
                for (int j = 0; j < 4; j++) {
                    int c = cbase + 32 * j;
                    float2 v2 = make_float2(lo[j] * scale, hi[j] * scale);
                    *reinterpret_cast<float2*>(&out[(size_t)r * C + c]) = v2;
                }
            }
        }
    } else {
        // split epilogue: cols [0,64) -> mu, [64,128) -> logstd
        // pair (c, c+1) always lies wholly in one half (c even, halves are 64 wide)
#pragma unroll
        for (int i = 0; i < 8; i++) {
            int r = m0 + ty + 16 * i;
            if (r < M) {
#pragma unroll
                for (int j = 0; j < 4; j++) {
                    int c = cbase + 32 * j;
                    float l, h;
                    UNPACK_F32X2(l, h, acc2[i][j]);
                    float2 v2;
                    float* dstp;
                    if (c < OUTC) {
                        v2 = make_float2(l + biasp[c], h + biasp[c + 1]);
                        dstp = &out[(size_t)r * OUTC + c];
                    } else {
                        v2 = make_float2(l + biasp2[c - OUTC], h + biasp2[c + 1 - OUTC]);
                        dstp = &out[(size_t)N_NODES * OUTC + (size_t)r * OUTC + (c - OUTC)];
                    }
                    *reinterpret_cast<float2*>(dstp) = v2;
                }
            }
        }
    }
}

// ---------------- launch -----------------------------------------------------
extern "C" void kernel_launch(void* const* d_in, const int* in_sizes, int n_in,
                              void* d_out, int out_size) {
    const float* x   = (const float*)d_in[0];
    const int*   ei  = (const int*)  d_in[1];
    const float* W1  = (const float*)d_in[2];
    const float* b1  = (const float*)d_in[3];
    const float* Wmu = (const float*)d_in[4];
    const float* bmu = (const float*)d_in[5];
    const float* Wls = (const float*)d_in[6];
    const float* bls = (const float*)d_in[7];
    float* out = (float*)d_out;

    const int n_edges = in_sizes[1] / 2;     // edge_index is [2, E]
    const int* src = ei;                     // edge_index[0]
    const int* dst = ei + n_edges;           // edge_index[1]

    const int smem = (128 * AST + C * C) * (int)sizeof(float);  // ~130 KB

    static bool configured = false;
    if (!configured) {
        cudaFuncSetAttribute(k_gemm<0>, cudaFuncAttributeMaxDynamicSharedMemorySize, smem);
        cudaFuncSetAttribute(k_gemm<1>, cudaFuncAttributeMaxDynamicSharedMemorySize, smem);
        configured = true;
    }

    // ---- CSR build (once, reused by both aggregations) ----
    k_cnt_init<<<(N_NODES + 255) / 256, 256>>>();
    k_count<<<(n_edges + 255) / 256, 256>>>(dst, n_edges);
    k_scan_block<<<SCAN_NB, SCAN_BS>>>();
    k_scan_add<<<(N_NODES + 255) / 256, 256>>>();
    k_fill<<<(n_edges + 255) / 256, 256>>>(src, dst, n_edges);

    // ---- layer 1: aggX = A_norm @ x ; h = rownorm(relu(aggX @ W1 + b1)) ----
    {
        unsigned t = (unsigned)N_NODES * 32u;
        k_agg<0><<<(t + 255) / 256, 256>>>(x);
    }
    k_gemm<0><<<(N_NODES + 127) / 128, 256, smem>>>(W1, nullptr, b1, nullptr, nullptr);

    // ---- layer 2: aggH = A_norm @ h ; [mu|logstd] = aggH @ [Wmu|Wls] + b ----
    {
        unsigned t = (unsigned)N_NODES * 32u;
        k_agg<1><<<(t + 255) / 256, 256>>>(nullptr);
    }
    k_gemm<1><<<(N_NODES + 127) / 128, 256, smem>>>(Wmu, Wls, bmu, bls, out);
}

// round 11
// speedup vs baseline: 1.2720x; 1.2005x over previous
#include <cuda_runtime.h>
#include <math.h>

#define N_NODES 100000
#define E_MAX   1600000
#define C 128
#define OUTC 64
#define AST 132          // padded stride, A tile (row-major, k contiguous)
#define TROWS 64         // GEMM tile rows (64 -> ~99KB smem -> 2 blocks/SM)
#define SCAN_BS 1024
#define SCAN_NB ((N_NODES + SCAN_BS - 1) / SCAN_BS)   // 98

// packed fp32 FMA (sm_103a FFMA2) — only reachable via PTX fma.rn.f32x2
#define FMA_F32X2(d, a, b, c) \
    asm("fma.rn.f32x2 %0, %1, %2, %3;" : "=l"(d) : "l"(a), "l"(b), "l"(c))
#define PACK_DUP_F32X2(d, v) \
    asm("mov.b64 %0, {%1, %1};" : "=l"(d) : "r"(__float_as_uint(v)))
#define UNPACK_F32X2(lo, hi, p) do {                                        \
    unsigned _ulo, _uhi;                                                    \
    asm("mov.b64 {%0, %1}, %2;" : "=r"(_ulo), "=r"(_uhi) : "l"(p));         \
    lo = __uint_as_float(_ulo); hi = __uint_as_float(_uhi); } while (0)

// ---------------- scratch (static device globals: allocation-free) ----------
// Referenced ONLY from device code (host-side use of __device__ symbols gives
// the host shadow address — round-3 lesson).
__device__ int   g_cnt[N_NODES];        // in-degree (edges only, no self-loop)
__device__ int   g_rowstart[N_NODES];   // CSR row offsets (exclusive scan)
__device__ int   g_cursor[N_NODES];     // fill cursors
__device__ int   g_bsum[SCAN_NB];       // scan block sums
__device__ int   g_csrc[E_MAX];         // CSR: src node per incoming edge slot
__device__ float g_dinv[N_NODES];
__device__ float g_aggX[(size_t)N_NODES * C];
__device__ float g_h[(size_t)N_NODES * C];
__device__ float g_aggH[(size_t)N_NODES * C];

// ---------------- CSR build --------------------------------------------------
__global__ void k_cnt_init() {
    int i = blockIdx.x * blockDim.x + threadIdx.x;
    if (i < N_NODES) g_cnt[i] = 0;
}

__global__ void k_count(const int* __restrict__ dst, int n_edges) {
    int e = blockIdx.x * blockDim.x + threadIdx.x;
    if (e < n_edges) atomicAdd(&g_cnt[dst[e]], 1);
}

// pass 1: per-block inclusive scan -> exclusive per element + block sums
__global__ void k_scan_block() {
    __shared__ int sh[SCAN_BS];
    int tid = threadIdx.x;
    int i = blockIdx.x * SCAN_BS + tid;
    int v = (i < N_NODES) ? g_cnt[i] : 0;
    sh[tid] = v;
    __syncthreads();
#pragma unroll
    for (int off = 1; off < SCAN_BS; off <<= 1) {
        int t = (tid >= off) ? sh[tid - off] : 0;
        __syncthreads();
        sh[tid] += t;
        __syncthreads();
    }
    if (i < N_NODES) g_rowstart[i] = sh[tid] - v;   // exclusive
    if (tid == SCAN_BS - 1) g_bsum[blockIdx.x] = sh[tid];
}

// pass 2 (merged): each 256-thread block lies in scan-block sb = b>>2;
// reduce g_bsum[0..sb-1] locally, add offset, init cursors, compute dinv.
__global__ void k_scan_add() {
    __shared__ int ssum[128];
    int tid = threadIdx.x;
    int sb = blockIdx.x >> 2;   // 1024/256 = 4 blocks per scan-block, aligned
    if (tid < 128) ssum[tid] = (tid < sb) ? g_bsum[tid] : 0;
    __syncthreads();
#pragma unroll
    for (int s = 64; s > 0; s >>= 1) {
        if (tid < s) ssum[tid] += ssum[tid + s];
        __syncthreads();
    }
    int off = ssum[0];
    int i = blockIdx.x * 256 + tid;
    if (i < N_NODES) {
        g_rowstart[i] += off;
        g_cursor[i] = 0;
        g_dinv[i] = rsqrtf((float)g_cnt[i] + 1.0f);
    }
}

__global__ void k_fill(const int* __restrict__ src, const int* __restrict__ dst,
                       int n_edges) {
    int e = blockIdx.x * blockDim.x + threadIdx.x;
    if (e >= n_edges) return;
    int d = dst[e];
    int p = atomicAdd(&g_cursor[d], 1);
    g_csrc[g_rowstart[d] + p] = src[e];
}

// ---------------- gather-aggregate: one warp per destination node ------------
// agg[n] = dinv[n]^2 * srcmat[n] + sum_{s in in(n)} dinv[n]*dinv[s]*srcmat[s]
// PHASE 0: x -> g_aggX     PHASE 1: g_h -> g_aggH
template<int PHASE>
__global__ void k_agg(const float* __restrict__ x) {
    const float* srcmat = (PHASE == 0) ? x : g_h;
    float* agg = (PHASE == 0) ? g_aggX : g_aggH;

    unsigned node = (blockIdx.x * blockDim.x + threadIdx.x) >> 5;
    unsigned lane = threadIdx.x & 31;
    if (node >= N_NODES) return;

    float din = g_dinv[node];
    // self-loop init
    float4 acc = reinterpret_cast<const float4*>(srcmat + (size_t)node * C)[lane];
    float cself = din * din;
    acc.x *= cself; acc.y *= cself; acc.z *= cself; acc.w *= cself;

    int beg = g_rowstart[node];
    int cnt = g_cnt[node];
    int j = 0;
    // 4-way unrolled edge loop: 4 rows in flight per warp (MLP)
    for (; j + 3 < cnt; j += 4) {
        int s0 = g_csrc[beg + j];
        int s1 = g_csrc[beg + j + 1];
        int s2 = g_csrc[beg + j + 2];
        int s3 = g_csrc[beg + j + 3];
        float c0 = din * g_dinv[s0];
        float c1 = din * g_dinv[s1];
        float c2 = din * g_dinv[s2];
        float c3 = din * g_dinv[s3];
        float4 v0 = reinterpret_cast<const float4*>(srcmat + (size_t)s0 * C)[lane];
        float4 v1 = reinterpret_cast<const float4*>(srcmat + (size_t)s1 * C)[lane];
        float4 v2 = reinterpret_cast<const float4*>(srcmat + (size_t)s2 * C)[lane];
        float4 v3 = reinterpret_cast<const float4*>(srcmat + (size_t)s3 * C)[lane];
        acc.x += c0 * v0.x + c1 * v1.x + c2 * v2.x + c3 * v3.x;
        acc.y += c0 * v0.y + c1 * v1.y + c2 * v2.y + c3 * v3.y;
        acc.z += c0 * v0.z + c1 * v1.z + c2 * v2.z + c3 * v3.z;
        acc.w += c0 * v0.w + c1 * v1.w + c2 * v2.w + c3 * v3.w;
    }
    for (; j < cnt; j++) {
        int s = g_csrc[beg + j];
        float c = din * g_dinv[s];
        float4 v = reinterpret_cast<const float4*>(srcmat + (size_t)s * C)[lane];
        acc.x += c * v.x; acc.y += c * v.y; acc.z += c * v.z; acc.w += c * v.w;
    }
    reinterpret_cast<float4*>(agg + (size_t)node * C)[lane] = acc;
}

__device__ __forceinline__ float f4get(const float4& v, int dk) {
    return dk == 0 ? v.x : dk == 1 ? v.y : dk == 2 ? v.z : v.w;
}

// ---------------- fused GEMM (packed f32x2): out = A @ B + bias --------------
// 64x128 block tile (64 rows -> ~99KB smem -> 2 blocks/SM, 4 warps/SMSP),
// 256 threads (16 tx x 16 ty). Thread owns rows r = ty + 16*i (i<4) and
// ADJACENT column pairs c = 2*tx + 32*j' (j'<4): the b operand
// (B[k][c], B[k][c+1]) is one aligned LDS.64 = ready f32x2 pair; accumulators
// are f32x2; a operand broadcast-packed via mov.b64 {a,a}.
// MODE 0: A=g_aggX, B=W1, bias=b1, out=g_h; epilogue ReLU + row L2-normalize.
// MODE 1: A=g_aggH, B=[Wmu|Wls] (inline concat), bias=[bmu|bls],
//         out=d_out split into mu / logstd regions.
template<int MODE>
__global__ void __launch_bounds__(256)
k_gemm(const float* __restrict__ Bp, const float* __restrict__ Bp2,
       const float* __restrict__ biasp, const float* __restrict__ biasp2,
       float* __restrict__ outp) {
    const float* A = (MODE == 0) ? g_aggX : g_aggH;
    float* out     = (MODE == 0) ? g_h : outp;
    const int M = N_NODES;

    extern __shared__ float sm[];
    float* As = sm;                // TROWS x AST (row-major, k contiguous)
    float* Bs = sm + TROWS * AST;  // 128 x 128 (row-major: Bs[k][c])

    int tid = threadIdx.x;
    int m0  = blockIdx.x * TROWS;

    // load B row-major. MODE 1 concatenates Wmu|Wls on the fly
    // (each float4 lies wholly in one 64-col half).
    for (int i = tid; i < C * C / 4; i += 256) {
        float4 v;
        if (MODE == 0) {
            v = reinterpret_cast<const float4*>(Bp)[i];
        } else {
            int k = i >> 5;          // row
            int c4 = (i & 31) * 4;   // col
            v = (c4 < OUTC)
                ? *reinterpret_cast<const float4*>(Bp  + k * OUTC + c4)
                : *reinterpret_cast<const float4*>(Bp2 + k * OUTC + (c4 - OUTC));
        }
        reinterpret_cast<float4*>(Bs)[i] = v;
    }
    // load A tile (TROWS rows, guarded), row-major padded stride
    for (int i = tid; i < TROWS * (C / 4); i += 256) {
        int r  = i >> 5;
        int c4 = i & 31;
        float4 v = make_float4(0.f, 0.f, 0.f, 0.f);
        if (m0 + r < M)
            v = reinterpret_cast<const float4*>(A + (size_t)(m0 + r) * C)[c4];
        reinterpret_cast<float4*>(As + r * AST)[c4] = v;
    }
    __syncthreads();

    int tx = tid & 15, ty = tid >> 4;
    int cbase = 2 * tx;              // column pair base; pairs at cbase + 32*j'

    unsigned long long acc2[4][4];
#pragma unroll
    for (int i = 0; i < 4; i++)
#pragma unroll
        for (int j = 0; j < 4; j++) acc2[i][j] = 0ULL;

    float4 a_cur[4];
#pragma unroll
    for (int i = 0; i < 4; i++)
        a_cur[i] = *reinterpret_cast<const float4*>(&As[(ty + 16 * i) * AST]);

#pragma unroll 1
    for (int kk = 0; kk < C - 4; kk += 4) {
        float4 a_nxt[4];
#pragma unroll
        for (int i = 0; i < 4; i++)
            a_nxt[i] = *reinterpret_cast<const float4*>(&As[(ty + 16 * i) * AST + kk + 4]);
#pragma unroll
        for (int dk = 0; dk < 4; dk++) {
            int k = kk + dk;
            unsigned long long b2[4];
#pragma unroll
            for (int j = 0; j < 4; j++)
                b2[j] = *reinterpret_cast<const unsigned long long*>(
                            &Bs[k * C + cbase + 32 * j]);
#pragma unroll
            for (int i = 0; i < 4; i++) {
                unsigned long long a2;
                PACK_DUP_F32X2(a2, f4get(a_cur[i], dk));
#pragma unroll
                for (int j = 0; j < 4; j++)
                    FMA_F32X2(acc2[i][j], a2, b2[j], acc2[i][j]);
            }
        }
#pragma unroll
        for (int i = 0; i < 4; i++) a_cur[i] = a_nxt[i];
    }
    // tail chunk (kk = C-4)
#pragma unroll
    for (int dk = 0; dk < 4; dk++) {
        int k = C - 4 + dk;
        unsigned long long b2[4];
#pragma unroll
        for (int j = 0; j < 4; j++)
            b2[j] = *reinterpret_cast<const unsigned long long*>(
                        &Bs[k * C + cbase + 32 * j]);
#pragma unroll
        for (int i = 0; i < 4; i++) {
            unsigned long long a2;
            PACK_DUP_F32X2(a2, f4get(a_cur[i], dk));
#pragma unroll
            for (int j = 0; j < 4; j++)
                FMA_F32X2(acc2[i][j], a2, b2[j], acc2[i][j]);
        }
    }

    if (MODE == 0) {
        // bias + ReLU + row L2 normalize (second ReLU in ref is a no-op: h>=0)
#pragma unroll
        for (int i = 0; i < 4; i++) {
            float lo[4], hi[4];
            float ss = 0.f;
#pragma unroll
            for (int j = 0; j < 4; j++) {
                int c = cbase + 32 * j;
                float l, h;
                UNPACK_F32X2(l, h, acc2[i][j]);
                l = fmaxf(l + biasp[c], 0.f);
                h = fmaxf(h + biasp[c + 1], 0.f);
                lo[j] = l; hi[j] = h;
                ss += l * l + h * h;
            }
            // reduce across the 16 tx lanes (bits 0..3 of lane id)
#pragma unroll
            for (int msk = 1; msk < 16; msk <<= 1)
                ss += __shfl_xor_sync(0xffffffffu, ss, msk);
            float scale = 1.f / fmaxf(sqrtf(ss), 1e-12f);
            int r = m0 + ty + 16 * i;
            if (r < M) {
#pragma unroll
                for (int j = 0; j < 4; j++) {
                    int c = cbase + 32 * j;
                    float2 v2 = make_float2(lo[j] * scale, hi[j] * scale);
                    *reinterpret_cast<float2*>(&out[(size_t)r * C + c]) = v2;
                }
            }
        }
    } else {
        // split epilogue: cols [0,64) -> mu, [64,128) -> logstd
        // pair (c, c+1) always lies wholly in one half (c even, halves 64 wide)
#pragma unroll
        for (int i = 0; i < 4; i++) {
            int r = m0 + ty + 16 * i;
            if (r < M) {
#pragma unroll
                for (int j = 0; j < 4; j++) {
                    int c = cbase + 32 * j;
                    float l, h;
                    UNPACK_F32X2(l, h, acc2[i][j]);
                    float2 v2;
                    float* dstp;
                    if (c < OUTC) {
                        v2 = make_float2(l + biasp[c], h + biasp[c + 1]);
                        dstp = &out[(size_t)r * OUTC + c];
                    } else {
                        v2 = make_float2(l + biasp2[c - OUTC], h + biasp2[c + 1 - OUTC]);
                        dstp = &out[(size_t)N_NODES * OUTC + (size_t)r * OUTC + (c - OUTC)];
                    }
                    *reinterpret_cast<float2*>(dstp) = v2;
                }
            }
        }
    }
}

// ---------------- launch -----------------------------------------------------
extern "C" void kernel_launch(void* const* d_in, const int* in_sizes, int n_in,
                              void* d_out, int out_size) {
    const float* x   = (const float*)d_in[0];
    const int*   ei  = (const int*)  d_in[1];
    const float* W1  = (const float*)d_in[2];
    const float* b1  = (const float*)d_in[3];
    const float* Wmu = (const float*)d_in[4];
    const float* bmu = (const float*)d_in[5];
    const float* Wls = (const float*)d_in[6];
    const float* bls = (const float*)d_in[7];
    float* out = (float*)d_out;

    const int n_edges = in_sizes[1] / 2;     // edge_index is [2, E]
    const int* src = ei;                     // edge_index[0]
    const int* dst = ei + n_edges;           // edge_index[1]

    const int smem = (TROWS * AST + C * C) * (int)sizeof(float);  // ~99.3 KB

    static bool configured = false;
    if (!configured) {
        cudaFuncSetAttribute(k_gemm<0>, cudaFuncAttributeMaxDynamicSharedMemorySize, smem);
        cudaFuncSetAttribute(k_gemm<1>, cudaFuncAttributeMaxDynamicSharedMemorySize, smem);
        configured = true;
    }

    // ---- CSR build (once, reused by both aggregations) ----
    k_cnt_init<<<(N_NODES + 255) / 256, 256>>>();
    k_count<<<(n_edges + 255) / 256, 256>>>(dst, n_edges);
    k_scan_block<<<SCAN_NB, SCAN_BS>>>();
    k_scan_add<<<(N_NODES + 255) / 256, 256>>>();
    k_fill<<<(n_edges + 255) / 256, 256>>>(src, dst, n_edges);

    // ---- layer 1: aggX = A_norm @ x ; h = rownorm(relu(aggX @ W1 + b1)) ----
    {
        unsigned t = (unsigned)N_NODES * 32u;
        k_agg<0><<<(t + 255) / 256, 256>>>(x);
    }
    k_gemm<0><<<(N_NODES + TROWS - 1) / TROWS, 256, smem>>>(W1, nullptr, b1, nullptr, nullptr);

    // ---- layer 2: aggH = A_norm @ h ; [mu|logstd] = aggH @ [Wmu|Wls] + b ----
    {
        unsigned t = (unsigned)N_NODES * 32u;
        k_agg<1><<<(t + 255) / 256, 256>>>(nullptr);
    }
    k_gemm<1><<<(N_NODES + TROWS - 1) / TROWS, 256, smem>>>(Wmu, Wls, bmu, bls, out);
}